// round 17
// baseline (speedup 1.0000x reference)
#include <cuda_runtime.h>
#include <cuda_fp16.h>
#include <cstdint>

// ---------------------------------------------------------------------------
// Problem constants
// ---------------------------------------------------------------------------
#define B_SZ   8192
#define IN_SZ  512
#define OUT_SZ 512
#define GP1    21            // grid_size + 1 coefficients per (o,i)
#define KPI    22            // k-slots per input feature (21 coeff + base)
#define KTOT   (IN_SZ * KPI) // 11264
#define STAGES (KTOT / 64)   // 176 stages of K=64

// Dense-GEMM reformulation:
//   out[b,o] = sum_k A[b,k] * Cmat[o,k],   k = i*22 + j
//   A[b, i*22+j]   = (j==idx: 1-t), (j==idx+1: t), (j==21: silu(xc)), else 0  (fp16)
//   Cmat[o, i*22+j]= (j<21: coeffs[o,i,j]), (j==21: base_w[o,i])               (fp16)
// R16: A is fully PRECOMPUTED in prep (184 MB scratch). Main kernel is a pure
// cp.async GEMM — no genA LDS/STS chain between barrier and MMAs (that chain
// held tensor at 50%; all in-loop generation/reordering variants R13-R15
// failed to hide it).

// ---------------------------------------------------------------------------
// Device scratch (static)
// ---------------------------------------------------------------------------
__device__ __half g_A[(size_t)B_SZ * KTOT];        // [b][k], 184 MB
__device__ __half g_Cmat[(size_t)OUT_SZ * KTOT];   // [o][k], 11.5 MB

// ---------------------------------------------------------------------------
// Helpers
// ---------------------------------------------------------------------------
__device__ __forceinline__ uint32_t smem_u32(const void* p) {
    uint32_t a;
    asm("{ .reg .u64 t; cvta.to.shared.u64 t, %1; cvt.u32.u64 %0, t; }" : "=r"(a) : "l"(p));
    return a;
}
__device__ __forceinline__ uint32_t sw128(uint32_t off) { return off ^ ((off >> 3) & 0x70); }

__device__ __forceinline__ void ldsm_x4(uint32_t addr, uint32_t r[4]) {
    asm volatile("ldmatrix.sync.aligned.m8n8.x4.shared.b16 {%0,%1,%2,%3}, [%4];"
                 : "=r"(r[0]), "=r"(r[1]), "=r"(r[2]), "=r"(r[3]) : "r"(addr));
}
__device__ __forceinline__ void mma16816(float d[4], const uint32_t a[4],
                                         uint32_t b0, uint32_t b1) {
    asm volatile("mma.sync.aligned.m16n8k16.row.col.f32.f16.f16.f32 "
                 "{%0,%1,%2,%3}, {%4,%5,%6,%7}, {%8,%9}, {%0,%1,%2,%3};"
                 : "+f"(d[0]), "+f"(d[1]), "+f"(d[2]), "+f"(d[3])
                 : "r"(a[0]), "r"(a[1]), "r"(a[2]), "r"(a[3]), "r"(b0), "r"(b1));
}

// ---------------------------------------------------------------------------
// Prep kernel: blocks [0, B_SZ) build one A row each; blocks >= B_SZ build Cmat.
// ---------------------------------------------------------------------------
#define CMAT_BLOCKS  (OUT_SZ * (KTOT / 8) / 256)  // 2816

__global__ void kan_prep(const float* __restrict__ x,
                         const float* __restrict__ coeffs,
                         const float* __restrict__ bw) {
    if (blockIdx.x < B_SZ) {
        // ---- A row b: 512 features x 22 halves, staged in SMEM ----
        __shared__ __half rowbuf[KTOT];            // 22.5 KB
        const int b = blockIdx.x;
        const int t = threadIdx.x;
#pragma unroll
        for (int rep = 0; rep < 2; rep++) {
            int i = t + rep * 256;
            float xv = x[(size_t)b * IN_SZ + i];   // coalesced
            float xc = fminf(1.0f, fmaxf(-1.0f, xv));
            float s  = xc / (1.0f + __expf(-xc));  // silu
            float u  = (xc + 1.0f) * 10.0f;        // in [0,20]
            int idx = (int)u;
            idx = idx > 19 ? 19 : idx;             // u==20 -> idx=19, t=1
            float tt = u - (float)idx;
            __half tmp[KPI];
#pragma unroll
            for (int j = 0; j < KPI; j++) tmp[j] = __ushort_as_half((unsigned short)0);
            tmp[idx]     = __float2half_rn(1.0f - tt);
            tmp[idx + 1] = __float2half_rn(tt);
            tmp[21]      = __float2half_rn(s);
#pragma unroll
            for (int j = 0; j < KPI; j++) rowbuf[i * KPI + j] = tmp[j];
        }
        __syncthreads();
        // coalesced copy to gmem: 1408 uint4 over 256 threads
        uint4* dst = (uint4*)(g_A + (size_t)b * KTOT);
        const uint4* src = (const uint4*)rowbuf;
        for (int j = t; j < KTOT / 8; j += 256) dst[j] = src[j];
    } else {
        // ---- Cmat fp16 [o][11264], k-linear 16B chunks ----
        int gch = (blockIdx.x - B_SZ) * 256 + threadIdx.x;
        int o  = gch / (KTOT / 8);
        int ch = gch - o * (KTOT / 8);
        int k0 = ch * 8;
        __half h[8];
#pragma unroll
        for (int v = 0; v < 8; v++) {
            int k = k0 + v;
            int i = k / KPI;
            int j = k - i * KPI;
            float val = (j < GP1) ? coeffs[(size_t)o * (IN_SZ * GP1) + (size_t)i * GP1 + j]
                                  : bw[(size_t)o * IN_SZ + i];
            h[v] = __float2half_rn(val);
        }
        *(uint4*)(g_Cmat + (size_t)o * KTOT + k0) = *(const uint4*)h;
    }
}

// ---------------------------------------------------------------------------
// Main GEMM: 256 CTAs (64 b x 4 o), CTA tile 128x128, 8 warps (256 thr),
// warp tile 64x32.  Stage K=64, double buffered, one barrier per stage.
// Pure cp.async producer path: threads 0-127 load A, 128-255 load B.
// SMEM: A[2][16KB] @0, B[2][16KB] @32768 -> 64 KB, 2 CTAs/SM.
// ---------------------------------------------------------------------------
#define A_REG  0
#define B_REG  32768
#define SMEM_SZ 65536

// Generic tile loader: 128 rows x 128B from src (row stride KTOT halves).
__device__ __forceinline__ void loadT(uint32_t sdst, const __half* src,
                                      int k0, int t2) {
#pragma unroll
    for (int rep = 0; rep < 8; rep++) {
        int q = t2 + rep * 128;             // [0,1024): 128 rows x 8 chunks of 16B
        int r = q >> 3;
        int c = q & 7;
        const __half* gp = src + (size_t)r * KTOT + (k0 + c * 8);
        uint32_t sa = sdst + sw128((uint32_t)r * 128 + (uint32_t)c * 16);
        asm volatile("cp.async.cg.shared.global [%0], [%1], 16;" :: "r"(sa), "l"(gp));
    }
}

__global__ __launch_bounds__(256, 2) void kan_main(float* __restrict__ out) {
    extern __shared__ char smem[];
    uint32_t sb = smem_u32(smem);
    const int tid   = threadIdx.x;
    const int lane  = tid & 31;
    const int wid   = tid >> 5;
    const int warpM = wid >> 2;             // 0..1 -> 64-row b stripe
    const int warpN = wid & 3;              // 0..3 -> 32-col o stripe
    const int ob = blockIdx.x * 128, bb = blockIdx.y * 128;

    const __half* Ag = g_A    + (size_t)bb * KTOT;
    const __half* Bg = g_Cmat + (size_t)ob * KTOT;

    float acc[4][4][4];
#pragma unroll
    for (int mt = 0; mt < 4; mt++)
#pragma unroll
        for (int nt = 0; nt < 4; nt++)
#pragma unroll
            for (int v = 0; v < 4; v++) acc[mt][nt][v] = 0.f;

    const uint32_t lrow = lane & 15;
    const uint32_t lkb  = (lane >> 4) * 16;

    // prologue: stage 0 in flight
    if (tid < 128) loadT(sb + A_REG, Ag, 0, tid);
    else           loadT(sb + B_REG, Bg, 0, tid - 128);
    asm volatile("cp.async.commit_group;");

    for (int s = 0; s < STAGES; s++) {
        const int cb = s & 1, nb = cb ^ 1;

        asm volatile("cp.async.wait_group 0;");   // stage s tiles complete
        __syncthreads();                          // visible; nb reads (s-1) done

        if (s + 1 < STAGES) {                     // issue next stage (async only)
            if (tid < 128) loadT(sb + A_REG + nb * 16384, Ag, (s + 1) * 64, tid);
            else           loadT(sb + B_REG + nb * 16384, Bg, (s + 1) * 64, tid - 128);
            asm volatile("cp.async.commit_group;");
        }

        const uint32_t Ab = sb + A_REG + cb * 16384;
        const uint32_t Bb = sb + B_REG + cb * 16384;
#pragma unroll
        for (int ks = 0; ks < 4; ks++) {
            uint32_t a[4][4];
#pragma unroll
            for (int mt = 0; mt < 4; mt++) {
                uint32_t row = (uint32_t)(warpM * 64 + mt * 16) + lrow;
                ldsm_x4(Ab + sw128(row * 128 + ks * 32 + lkb), a[mt]);
            }
            uint32_t bf[2][4];
#pragma unroll
            for (int bt = 0; bt < 2; bt++) {
                uint32_t nrow = (uint32_t)(warpN * 32 + bt * 16) + lrow;
                ldsm_x4(Bb + sw128(nrow * 128 + ks * 32 + lkb), bf[bt]);
            }
#pragma unroll
            for (int mt = 0; mt < 4; mt++)
#pragma unroll
                for (int nt = 0; nt < 4; nt++) {
                    int bt = nt >> 1, hi = nt & 1;
                    mma16816(acc[mt][nt], a[mt], bf[bt][hi], bf[bt][hi + 2]);
                }
        }
    }

    // epilogue: direct f32 stores
#pragma unroll
    for (int mt = 0; mt < 4; mt++) {
        int r0 = bb + warpM * 64 + mt * 16 + (lane >> 2);
#pragma unroll
        for (int nt = 0; nt < 4; nt++) {
            int c0 = ob + warpN * 32 + nt * 8 + (lane & 3) * 2;
            *(float2*)&out[(size_t)r0 * OUT_SZ + c0] =
                make_float2(acc[mt][nt][0], acc[mt][nt][1]);
            *(float2*)&out[(size_t)(r0 + 8) * OUT_SZ + c0] =
                make_float2(acc[mt][nt][2], acc[mt][nt][3]);
        }
    }
}

// ---------------------------------------------------------------------------
// Launch: x [8192,512], coeffs [512,512,21], base_w [512,512] -> out f32 [8192,512]
// ---------------------------------------------------------------------------
extern "C" void kernel_launch(void* const* d_in, const int* in_sizes, int n_in,
                              void* d_out, int out_size) {
    const float* x      = (const float*)d_in[0];
    const float* coeffs = (const float*)d_in[1];
    const float* base_w = (const float*)d_in[2];
    float* out = (float*)d_out;

    cudaFuncSetAttribute(kan_main, cudaFuncAttributeMaxDynamicSharedMemorySize, SMEM_SZ);

    kan_prep<<<B_SZ + CMAT_BLOCKS, 256>>>(x, coeffs, base_w);
    kan_main<<<dim3(OUT_SZ / 128, B_SZ / 128), 256, SMEM_SZ>>>(out);
}